// round 11
// baseline (speedup 1.0000x reference)
#include <cuda_runtime.h>
#include <cuda_bf16.h>
#include <math.h>

#define Bn 4
#define Qn 1024
#define Dn 256
#define GH 64
#define TQ 64
#define TK 64
#define PITCH 72    // bf16 pitch for mma smem tiles
#define BPITCH 66   // fp32 pitch for bil staging

typedef unsigned int uint;

__device__ __nv_bfloat16 g_qWb[Bn * Qn * Dn];
__device__ __nv_bfloat16 g_qb[Bn * Qn * Dn];
__device__ __nv_bfloat16 g_Wt[Dn * Dn];       // W transposed: g_Wt[n*Dn+k] = W[k][n]

__device__ __forceinline__ uint packbf2(float lo, float hi) {
    uint r;
    asm("cvt.rn.bf16x2.f32 %0, %1, %2;" : "=r"(r) : "f"(hi), "f"(lo));
    return r;
}

// packed silu on bf16x2: x * sigmoid(x); 1 MUFU for 2 lanes.
__device__ __forceinline__ uint silu2(uint x) {
    const uint H = 0x3F003F00u;   // bf16x2 (0.5, 0.5)
    uint t;
    asm("mul.rn.bf16x2 %0, %1, %2;" : "=r"(t) : "r"(x), "r"(H));
    asm("tanh.approx.bf16x2 %0, %1;" : "=r"(t) : "r"(t));
    asm("fma.rn.bf16x2 %0, %1, %2, %3;" : "=r"(t) : "r"(t), "r"(H), "r"(H));
    uint r;
    asm("mul.rn.bf16x2 %0, %1, %2;" : "=r"(r) : "r"(x), "r"(t));
    return r;
}

#define HFMA2BF(d, a, b, c) \
    asm("fma.rn.bf16x2 %0, %1, %2, %3;" : "=r"(d) : "r"(a), "r"(b), "r"(c))

__device__ __forceinline__ void mma16816(float* c, uint a0, uint a1, uint a2, uint a3,
                                         uint b0, uint b1) {
    asm("mma.sync.aligned.m16n8k16.row.col.f32.bf16.bf16.f32 "
        "{%0,%1,%2,%3},{%4,%5,%6,%7},{%8,%9},{%0,%1,%2,%3};"
        : "+f"(c[0]), "+f"(c[1]), "+f"(c[2]), "+f"(c[3])
        : "r"(a0), "r"(a1), "r"(a2), "r"(a3), "r"(b0), "r"(b1));
}

__device__ __forceinline__ void mma16808(float& c0, float& c1, float& c2, float& c3,
                                         uint a0, uint a1, uint b0) {
    asm("mma.sync.aligned.m16n8k8.row.col.f32.bf16.bf16.f32 "
        "{%0,%1,%2,%3},{%4,%5},{%6},{%0,%1,%2,%3};"
        : "+f"(c0), "+f"(c1), "+f"(c2), "+f"(c3)
        : "r"(a0), "r"(a1), "r"(b0));
}

// ---------------------------------------------------------------------------
// Convert kernel: q -> bf16 (float4-wide), W -> transposed bf16 (tiled).
// ---------------------------------------------------------------------------
__global__ __launch_bounds__(256) void convert_kernel(
    const float* __restrict__ q, const float* __restrict__ W)
{
    __shared__ float tile[32][33];
    const int bid = blockIdx.x;
    const int tid = threadIdx.x;
    if (bid < 1024) {
        int i = bid * 256 + tid;
        float4 v = ((const float4*)q)[i];
        uint2 o;
        o.x = packbf2(v.x, v.y);
        o.y = packbf2(v.z, v.w);
        ((uint2*)g_qb)[i] = o;
    } else {
        // W transpose via smem tile: 8x8 grid of 32x32 tiles, both sides coalesced
        int t  = bid - 1024;          // 0..63
        int tr = t >> 3, tc = t & 7;
        int r = tid >> 5, c = tid & 31;
#pragma unroll
        for (int rr = 0; rr < 32; rr += 8)
            tile[r + rr][c] = W[(tr * 32 + r + rr) * Dn + tc * 32 + c];
        __syncthreads();
#pragma unroll
        for (int rr = 0; rr < 32; rr += 8)
            g_Wt[(tc * 32 + r + rr) * Dn + tr * 32 + c] = __float2bfloat16(tile[c][r + rr]);
    }
}

// ---------------------------------------------------------------------------
// qW GEMM via mma: g_qWb = g_qb @ W.
// ---------------------------------------------------------------------------
__global__ __launch_bounds__(256) void qw_mma_kernel()
{
    __shared__ __align__(16) __nv_bfloat16 At[64 * PITCH];
    __shared__ __align__(16) __nv_bfloat16 Bt[64 * PITCH];

    const int tid  = threadIdx.x;
    const int warp = tid >> 5;
    const int lane = tid & 31;
    const int m    = lane & 3;
    const int g    = lane >> 2;
    const int wq   = warp & 3;
    const int wk   = warp >> 2;
    const int bm   = blockIdx.x * 64;
    const int bn   = blockIdx.y * 64;

    float bacc[4][4];
#pragma unroll
    for (int n = 0; n < 4; n++)
#pragma unroll
        for (int j = 0; j < 4; j++) bacc[n][j] = 0.f;

#pragma unroll 1
    for (int k0 = 0; k0 < Dn; k0 += 64) {
        __syncthreads();
#pragma unroll
        for (int rep = 0; rep < 2; rep++) {
            int idx = tid + rep * 256;
            int r = idx >> 3, c8 = (idx & 7) * 8;
            *(uint4*)&At[r * PITCH + c8] = *(const uint4*)&g_qb[(bm + r) * Dn + k0 + c8];
            *(uint4*)&Bt[r * PITCH + c8] = *(const uint4*)&g_Wt[(bn + r) * Dn + k0 + c8];
        }
        __syncthreads();
#pragma unroll
        for (int s2 = 0; s2 < 4; s2++) {
            const int acol = 16 * s2 + 2 * m;
            const int arow = 16 * wq + g;
            uint a0 = *(const uint*)&At[arow * PITCH + acol];
            uint a1 = *(const uint*)&At[(arow + 8) * PITCH + acol];
            uint a2 = *(const uint*)&At[arow * PITCH + acol + 8];
            uint a3 = *(const uint*)&At[(arow + 8) * PITCH + acol + 8];
#pragma unroll
            for (int n = 0; n < 4; n++) {
                const int brow = 32 * wk + 8 * n + g;
                uint b0 = *(const uint*)&Bt[brow * PITCH + acol];
                uint b1 = *(const uint*)&Bt[brow * PITCH + acol + 8];
                mma16816(bacc[n], a0, a1, a2, a3, b0, b1);
            }
        }
    }
#pragma unroll
    for (int n = 0; n < 4; n++) {
        int row = bm + 16 * wq + g;
        int col = bn + 32 * wk + 8 * n + 2 * m;
        *(__nv_bfloat162*)&g_qWb[row * Dn + col] =
            __floats2bfloat162_rn(bacc[n][0], bacc[n][1]);
        *(__nv_bfloat162*)&g_qWb[(row + 8) * Dn + col] =
            __floats2bfloat162_rn(bacc[n][2], bacc[n][3]);
    }
}

// ---------------------------------------------------------------------------
// Fused kernel: bilinear (mma) + compacted geo MLP (mma + GA table).
// ---------------------------------------------------------------------------
__global__ __launch_bounds__(256, 2) void edge_head_mma_kernel(
    const float* __restrict__ coords,
    const int*   __restrict__ amask,
    const float* __restrict__ w1,
    const float* __restrict__ b1,
    const float* __restrict__ w2,
    const float* __restrict__ b2,
    const float* __restrict__ w3,
    const float* __restrict__ b3,
    const float* __restrict__ bias,
    float* __restrict__ out)
{
    // union region: bilinear tiles (18432B x2) / GA feature table (16384B)
    __shared__ __align__(16) char uraw[TQ * PITCH * 2 + TK * PITCH * 2];
    __shared__ float  bilS[TQ * BPITCH];
    __shared__ __align__(16) uint4 B4s[4 * 4 * 32];   // layer-2 B frag pairs, 8KB
    __shared__ __align__(8) float2 b1p[32], b2p[32];
    __shared__ uint   w3bp[32];
    __shared__ float  cxq[TQ], cyq[TQ], cxk[TK], cyk[TK];
    __shared__ int    aqs[TQ], aks[TK];
    __shared__ int    sActQ[TQ], sActK[TK];
    __shared__ int    sKoff[5], sRa;
    __shared__ float  cadd;

    __nv_bfloat16* qWt = (__nv_bfloat16*)uraw;
    __nv_bfloat16* qt  = (__nv_bfloat16*)(uraw + TQ * PITCH * 2);
    uint*          GAs = (uint*)uraw;     // [16 k][64 row][4] bf16x2 feature pairs

    const int tid  = threadIdx.x;
    const int warp = tid >> 5;
    const int lane = tid & 31;
    const int m    = lane & 3;
    const int g    = lane >> 2;
    const int wq   = warp & 3;
    const int wk   = warp >> 2;
    const int b    = blockIdx.z;
    const int q0   = blockIdx.y * TQ;
    const int k0   = blockIdx.x * TK;

    // ---- prewrite whole out tile to -1e9 ----
    {
        const float4 neg = make_float4(-1e9f, -1e9f, -1e9f, -1e9f);
#pragma unroll
        for (int e = tid; e < 1024; e += 256) {
            int r = e >> 4, c = (e & 15) * 4;
            *(float4*)&out[((long)(b * Qn + q0 + r)) * Qn + k0 + c] = neg;
        }
    }

    if (tid < GH) {
        int i = tid;
        int gq = b * Qn + q0 + i;
        cxq[i] = coords[gq * 2 + 0]; cyq[i] = coords[gq * 2 + 1];
        aqs[i] = amask[gq];
    } else if (tid < 2 * GH) {
        int i = tid - GH;
        int gk = b * Qn + k0 + i;
        cxk[i] = coords[gk * 2 + 0]; cyk[i] = coords[gk * 2 + 1];
        aks[i] = amask[gk];
    }
    if (tid == 0) cadd = b3[0] + bias[0];

    // layer-2 B fragment pairs
#pragma unroll
    for (int e = tid; e < 512; e += 256) {
        int s  = e >> 7;
        int np = (e >> 5) & 3;
        int ln = e & 31;
        int em = ln & 3, eg = ln >> 2;
        int kk = 16 * s + 2 * em;
        uint4 v;
        int n0 = 8 * (2 * np) + eg;
        v.x = packbf2(w2[kk * GH + n0],       w2[(kk + 1) * GH + n0]);
        v.y = packbf2(w2[(kk + 8) * GH + n0], w2[(kk + 9) * GH + n0]);
        int n1 = 8 * (2 * np + 1) + eg;
        v.z = packbf2(w2[kk * GH + n1],       w2[(kk + 1) * GH + n1]);
        v.w = packbf2(w2[(kk + 8) * GH + n1], w2[(kk + 9) * GH + n1]);
        B4s[e] = v;
    }
    if (tid < 32) {
        int nb = tid >> 2, mm = tid & 3;
        int c = 8 * nb + 2 * mm;
        b1p[tid]  = make_float2(b1[c], b1[c + 1]);
        b2p[tid]  = make_float2(b2[c], b2[c + 1]);
        w3bp[tid] = packbf2(w3[c], w3[c + 1]);
    }

    uint W1B[8];
#pragma unroll
    for (int nb = 0; nb < 8; nb++) {
        int nn = 8 * nb + g;
        W1B[nb] = (m < 3) ? packbf2(w1[(2 * m) * GH + nn], w1[(2 * m + 1) * GH + nn]) : 0u;
    }

    __syncthreads();   // aqs/aks ready

    // ---- compaction: warp0 -> active q rows, warp1 -> active k cols ----
    if (warp == 0) {
        uint m0 = __ballot_sync(0xffffffffu, aqs[lane] != 0);
        uint m1 = __ballot_sync(0xffffffffu, aqs[lane + 32] != 0);
        int c0 = __popc(m0);
        if (m0 & (1u << lane)) sActQ[__popc(m0 & ((1u << lane) - 1u))] = lane;
        if (m1 & (1u << lane)) sActQ[c0 + __popc(m1 & ((1u << lane) - 1u))] = lane + 32;
        if (lane == 0) sRa = c0 + __popc(m1);
    } else if (warp == 1) {
        uint m0 = __ballot_sync(0xffffffffu, aks[lane] != 0);
        uint m1 = __ballot_sync(0xffffffffu, aks[lane + 32] != 0);
        int c0 = __popc(m0);
        if (m0 & (1u << lane)) sActK[__popc(m0 & ((1u << lane) - 1u))] = lane;
        if (m1 & (1u << lane)) sActK[c0 + __popc(m1 & ((1u << lane) - 1u))] = lane + 32;
        if (lane == 0) {
            sKoff[0] = 0;
            sKoff[1] = __popc(m0 & 0xFFFFu);
            sKoff[2] = c0;
            sKoff[3] = c0 + __popc(m1 & 0xFFFFu);
            sKoff[4] = c0 + __popc(m1);
        }
    }
    __syncthreads();
    // pad compacted q list (duplicates suppressed at write by rc<Ra predicate)
    if (tid < 64 && tid >= sRa && sRa > 0) sActQ[tid] = sActQ[sRa - 1];

    // ---- bilinear via mma ----
    float bacc[4][4];
#pragma unroll
    for (int n = 0; n < 4; n++)
#pragma unroll
        for (int j = 0; j < 4; j++) bacc[n][j] = 0.f;

#pragma unroll 1
    for (int d0 = 0; d0 < Dn; d0 += 64) {
        __syncthreads();
#pragma unroll
        for (int rep = 0; rep < 2; rep++) {
            int idx = tid + rep * 256;
            int r = idx >> 3, c8 = (idx & 7) * 8;
            *(uint4*)&qWt[r * PITCH + c8] =
                *(const uint4*)&g_qWb[(b * Qn + q0 + r) * Dn + d0 + c8];
            *(uint4*)&qt[r * PITCH + c8] =
                *(const uint4*)&g_qb[(b * Qn + k0 + r) * Dn + d0 + c8];
        }
        __syncthreads();
#pragma unroll
        for (int s2 = 0; s2 < 4; s2++) {
            const int acol = 16 * s2 + 2 * m;
            const int arow = 16 * wq + g;
            uint a0 = *(const uint*)&qWt[arow * PITCH + acol];
            uint a1 = *(const uint*)&qWt[(arow + 8) * PITCH + acol];
            uint a2 = *(const uint*)&qWt[arow * PITCH + acol + 8];
            uint a3 = *(const uint*)&qWt[(arow + 8) * PITCH + acol + 8];
#pragma unroll
            for (int n = 0; n < 4; n++) {
                const int brow = 32 * wk + 8 * n + g;
                uint b0 = *(const uint*)&qt[brow * PITCH + acol];
                uint b1v = *(const uint*)&qt[brow * PITCH + acol + 8];
                mma16816(bacc[n], a0, a1, a2, a3, b0, b1v);
            }
        }
    }
    __syncthreads();
#pragma unroll
    for (int n = 0; n < 4; n++) {
        int row = 16 * wq + g;
        int col = 32 * wk + 8 * n + 2 * m;
        *(float2*)&bilS[row * BPITCH + col]       = make_float2(bacc[n][0], bacc[n][1]);
        *(float2*)&bilS[(row + 8) * BPITCH + col] = make_float2(bacc[n][2], bacc[n][3]);
    }

    // ---- MLP phase: 4 passes of 16 k-slots; flat compacted work items ----
    const int Ra = sRa;
    const int RC = (Ra + 15) >> 4;                    // row chunks (0..4)
    const uint MR = RC ? (65536u / (uint)RC + 1u) : 0u; // magic for /RC
    const float caddv = cadd;

#pragma unroll 1
    for (int p = 0; p < 4; p++) {
        __syncthreads();   // prior GA/tile reads done before overwrite
        // GA features for k-slots [16p,16p+16), all 64 rows (skip inactive k)
#pragma unroll
        for (int r = 0; r < 4; r++) {
            int e   = tid + 256 * r;
            int kl  = e >> 6;
            int row = e & 63;
            int k   = 16 * p + kl;
            if (aks[k] != 0) {
                float dxv = cxq[row] - cxk[k];
                float dyv = cyq[row] - cyk[k];
                float d2v = fmaf(dxv, dxv, dyv * dyv);
                float dsv = sqrtf(d2v + 1e-8f);
                bool  mzv = (fabsf(dxv) < 1e-6f) && (fabsf(dyv) < 1e-6f);
                float xsv = mzv ? 1e-6f : dxv;
                float ysv = mzv ? 1e-6f : dyv;
                float rhv = rsqrtf(fmaf(xsv, xsv, ysv * ysv));
                uint4 gv;
                gv.x = packbf2(dxv, dyv);
                gv.y = packbf2(dsv, d2v);
                gv.z = packbf2(ysv * rhv, xsv * rhv);
                gv.w = 0u;
                *(uint4*)&GAs[(kl * 64 + row) * 4] = gv;
            }
        }
        __syncthreads();

        const int kbase  = sKoff[p];
        const int nItems = (sKoff[p + 1] - kbase) * RC;

#pragma unroll 1
        for (int t = warp; t < nItems; t += 8) {
            const int kq    = (int)(((uint)t * MR) >> 16);   // t / RC
            const int chunk = t - kq * RC;
            const int k     = sActK[kbase + kq];             // tile-local k (active)
            const int kl    = k - 16 * p;
            const int gk    = k0 + k;

            const int rc0  = 16 * chunk + g;
            const int rc1  = rc0 + 8;
            const int row0 = sActQ[rc0];
            const int row1 = sActQ[rc1];

            const uint GA0 = GAs[(kl * 64 + row0) * 4 + m];
            const uint GA1 = GAs[(kl * 64 + row1) * 4 + m];

            float acc2[8][4];
#pragma unroll
            for (int n = 0; n < 8; n++) {
                float2 bv = b2p[n * 4 + m];
                acc2[n][0] = bv.x; acc2[n][1] = bv.y;
                acc2[n][2] = bv.x; acc2[n][3] = bv.y;
            }

#pragma unroll
            for (int s = 0; s < 4; s++) {
                uint a0, a1, a2, a3;
                {
                    int nb = 2 * s;
                    float2 bv = b1p[nb * 4 + m];
                    float c0 = bv.x, c1 = bv.y, c2 = bv.x, c3 = bv.y;
                    mma16808(c0, c1, c2, c3, GA0, GA1, W1B[nb]);
                    a0 = silu2(packbf2(c0, c1));
                    a1 = silu2(packbf2(c2, c3));
                }
                {
                    int nb = 2 * s + 1;
                    float2 bv = b1p[nb * 4 + m];
                    float c0 = bv.x, c1 = bv.y, c2 = bv.x, c3 = bv.y;
                    mma16808(c0, c1, c2, c3, GA0, GA1, W1B[nb]);
                    a2 = silu2(packbf2(c0, c1));
                    a3 = silu2(packbf2(c2, c3));
                }
                const uint4* Brow = &B4s[(s * 4) * 32 + lane];
#pragma unroll
                for (int np = 0; np < 4; np++) {
                    uint4 Bv = Brow[np * 32];
                    mma16816(acc2[2 * np],     a0, a1, a2, a3, Bv.x, Bv.y);
                    mma16816(acc2[2 * np + 1], a0, a1, a2, a3, Bv.z, Bv.w);
                }
            }

            uint P0 = 0u, P1 = 0u;
#pragma unroll
            for (int n = 0; n < 8; n++) {
                uint wv = w3bp[n * 4 + m];
                uint s01 = silu2(packbf2(acc2[n][0], acc2[n][1]));
                uint s23 = silu2(packbf2(acc2[n][2], acc2[n][3]));
                HFMA2BF(P0, s01, wv, P0);
                HFMA2BF(P1, s23, wv, P1);
            }
            float p0 = __uint_as_float(P0 << 16) + __uint_as_float(P0 & 0xffff0000u);
            float p1 = __uint_as_float(P1 << 16) + __uint_as_float(P1 & 0xffff0000u);
            p0 += __shfl_xor_sync(0xffffffffu, p0, 1);
            p0 += __shfl_xor_sync(0xffffffffu, p0, 2);
            p1 += __shfl_xor_sync(0xffffffffu, p1, 1);
            p1 += __shfl_xor_sync(0xffffffffu, p1, 2);

            if (m == (t & 3)) {
                const int qi0 = q0 + row0, qi1 = q0 + row1;
                if (rc0 < Ra)
                    out[((long)(b * Qn + qi0)) * Qn + gk] =
                        (qi0 == gk) ? 0.f : p0 + bilS[row0 * BPITCH + k] + caddv;
                if (rc1 < Ra)
                    out[((long)(b * Qn + qi1)) * Qn + gk] =
                        (qi1 == gk) ? 0.f : p1 + bilS[row1 * BPITCH + k] + caddv;
            }
        }
    }
}

// ---------------------------------------------------------------------------
extern "C" void kernel_launch(void* const* d_in, const int* in_sizes, int n_in,
                              void* d_out, int out_size)
{
    const float* q      = (const float*)d_in[0];
    const float* coords = (const float*)d_in[1];
    const int*   amask  = (const int*)d_in[2];
    const float* W      = (const float*)d_in[3];
    const float* w1     = (const float*)d_in[4];
    const float* b1     = (const float*)d_in[5];
    const float* w2     = (const float*)d_in[6];
    const float* b2     = (const float*)d_in[7];
    const float* w3     = (const float*)d_in[8];
    const float* b3     = (const float*)d_in[9];
    const float* bias   = (const float*)d_in[10];
    float* out = (float*)d_out;

    convert_kernel<<<1088, 256>>>(q, W);
    {
        dim3 grid((Bn * Qn) / 64, Dn / 64);
        qw_mma_kernel<<<grid, 256>>>();
    }
    {
        dim3 grid(Qn / TK, Qn / TQ, Bn);
        edge_head_mma_kernel<<<grid, 256>>>(coords, amask,
                                            w1, b1, w2, b2, w3, b3, bias, out);
    }
}

// round 12
// speedup vs baseline: 1.6960x; 1.6960x over previous
#include <cuda_runtime.h>
#include <cuda_bf16.h>
#include <math.h>

#define Bn 4
#define Qn 1024
#define Dn 256
#define GH 64
#define TQ 64
#define TK 64
#define PITCH 72    // bf16 pitch for mma smem tiles
#define BPITCH 66   // fp32 pitch for bil staging

typedef unsigned int uint;

__device__ __nv_bfloat16 g_qWb[Bn * Qn * Dn];
__device__ __nv_bfloat16 g_qb[Bn * Qn * Dn];

__device__ __forceinline__ uint packbf2(float lo, float hi) {
    uint r;
    asm("cvt.rn.bf16x2.f32 %0, %1, %2;" : "=r"(r) : "f"(hi), "f"(lo));
    return r;
}

// packed silu on bf16x2: x * sigmoid(x); 1 MUFU for 2 lanes.
__device__ __forceinline__ uint silu2(uint x) {
    const uint H = 0x3F003F00u;   // bf16x2 (0.5, 0.5)
    uint t;
    asm("mul.rn.bf16x2 %0, %1, %2;" : "=r"(t) : "r"(x), "r"(H));
    asm("tanh.approx.bf16x2 %0, %1;" : "=r"(t) : "r"(t));
    asm("fma.rn.bf16x2 %0, %1, %2, %3;" : "=r"(t) : "r"(t), "r"(H), "r"(H));
    uint r;
    asm("mul.rn.bf16x2 %0, %1, %2;" : "=r"(r) : "r"(x), "r"(t));
    return r;
}

#define HFMA2BF(d, a, b, c) \
    asm("fma.rn.bf16x2 %0, %1, %2, %3;" : "=r"(d) : "r"(a), "r"(b), "r"(c))

__device__ __forceinline__ void mma16816(float* c, uint a0, uint a1, uint a2, uint a3,
                                         uint b0, uint b1) {
    asm("mma.sync.aligned.m16n8k16.row.col.f32.bf16.bf16.f32 "
        "{%0,%1,%2,%3},{%4,%5,%6,%7},{%8,%9},{%0,%1,%2,%3};"
        : "+f"(c[0]), "+f"(c[1]), "+f"(c[2]), "+f"(c[3])
        : "r"(a0), "r"(a1), "r"(a2), "r"(a3), "r"(b0), "r"(b1));
}

__device__ __forceinline__ void mma16808(float& c0, float& c1, float& c2, float& c3,
                                         uint a0, uint a1, uint b0) {
    asm("mma.sync.aligned.m16n8k8.row.col.f32.bf16.bf16.f32 "
        "{%0,%1,%2,%3},{%4,%5},{%6},{%0,%1,%2,%3};"
        : "+f"(c0), "+f"(c1), "+f"(c2), "+f"(c3)
        : "r"(a0), "r"(a1), "r"(b0));
}

// ---------------------------------------------------------------------------
// Fused prep kernel: qW = q @ W via mma (fp32 inputs converted in staging),
// writes g_qWb (bf16). bn==0 blocks also side-write g_qb (q -> bf16).
// W is transposed in-kernel through an fp32 smem scratch.
// ---------------------------------------------------------------------------
__global__ __launch_bounds__(256) void prep_kernel(
    const float* __restrict__ q, const float* __restrict__ W)
{
    __shared__ __align__(16) __nv_bfloat16 At[64 * PITCH];   // [m][k] bf16
    __shared__ __align__(16) __nv_bfloat16 Bt[64 * PITCH];   // [n][k] bf16
    __shared__ __align__(16) float Ws[64][68];               // fp32 W tile [k][n]

    const int tid  = threadIdx.x;
    const int warp = tid >> 5;
    const int lane = tid & 31;
    const int m    = lane & 3;
    const int g    = lane >> 2;
    const int wq   = warp & 3;
    const int wk   = warp >> 2;
    const int bm   = blockIdx.x * 64;
    const int bn   = blockIdx.y * 64;

    float bacc[4][4];
#pragma unroll
    for (int n = 0; n < 4; n++)
#pragma unroll
        for (int j = 0; j < 4; j++) bacc[n][j] = 0.f;

#pragma unroll 1
    for (int k0 = 0; k0 < Dn; k0 += 64) {
        __syncthreads();   // prior mma reads done before overwrite
        // ---- A tile: q fp32 -> bf16 (+ side-write g_qb from bn==0) ----
#pragma unroll
        for (int rep = 0; rep < 4; rep++) {
            int idx = rep * 256 + tid;          // 0..1023
            int r = idx >> 4, c4 = idx & 15;
            float4 v = *(const float4*)&q[(bm + r) * Dn + k0 + c4 * 4];
            uint2 o;
            o.x = packbf2(v.x, v.y);
            o.y = packbf2(v.z, v.w);
            *(uint2*)&At[r * PITCH + c4 * 4] = o;
            if (bn == 0)
                *(uint2*)&g_qb[(bm + r) * Dn + k0 + c4 * 4] = o;
        }
        // ---- W tile fp32, coalesced [k][n] ----
#pragma unroll
        for (int rep = 0; rep < 4; rep++) {
            int idx = rep * 256 + tid;
            int kr = idx >> 4, nc4 = idx & 15;
            float4 w = *(const float4*)&W[(k0 + kr) * Dn + bn + nc4 * 4];
            *(float4*)&Ws[kr][nc4 * 4] = w;
        }
        __syncthreads();
        // ---- transpose-pack Ws -> Bt[n][k] bf16 ----
#pragma unroll
        for (int rep = 0; rep < 8; rep++) {
            int idx = rep * 256 + tid;          // 0..2047
            int nc = idx & 63, kp = idx >> 6;   // kp 0..31 (k pairs)
            uint v = packbf2(Ws[2 * kp][nc], Ws[2 * kp + 1][nc]);
            *(uint*)&Bt[nc * PITCH + 2 * kp] = v;
        }
        __syncthreads();
        // ---- mma ----
#pragma unroll
        for (int s2 = 0; s2 < 4; s2++) {
            const int acol = 16 * s2 + 2 * m;
            const int arow = 16 * wq + g;
            uint a0 = *(const uint*)&At[arow * PITCH + acol];
            uint a1 = *(const uint*)&At[(arow + 8) * PITCH + acol];
            uint a2 = *(const uint*)&At[arow * PITCH + acol + 8];
            uint a3 = *(const uint*)&At[(arow + 8) * PITCH + acol + 8];
#pragma unroll
            for (int n = 0; n < 4; n++) {
                const int brow = 32 * wk + 8 * n + g;
                uint b0 = *(const uint*)&Bt[brow * PITCH + acol];
                uint b1 = *(const uint*)&Bt[brow * PITCH + acol + 8];
                mma16816(bacc[n], a0, a1, a2, a3, b0, b1);
            }
        }
    }
#pragma unroll
    for (int n = 0; n < 4; n++) {
        int row = bm + 16 * wq + g;
        int col = bn + 32 * wk + 8 * n + 2 * m;
        *(__nv_bfloat162*)&g_qWb[row * Dn + col] =
            __floats2bfloat162_rn(bacc[n][0], bacc[n][1]);
        *(__nv_bfloat162*)&g_qWb[(row + 8) * Dn + col] =
            __floats2bfloat162_rn(bacc[n][2], bacc[n][3]);
    }
}

// ---------------------------------------------------------------------------
// Fused kernel: bilinear (mma) + geo MLP (mma + shared GA feature table).
// (R10 version — known 166.4 us.)
// ---------------------------------------------------------------------------
__global__ __launch_bounds__(256, 2) void edge_head_mma_kernel(
    const float* __restrict__ coords,
    const int*   __restrict__ amask,
    const float* __restrict__ w1,
    const float* __restrict__ b1,
    const float* __restrict__ w2,
    const float* __restrict__ b2,
    const float* __restrict__ w3,
    const float* __restrict__ b3,
    const float* __restrict__ bias,
    float* __restrict__ out)
{
    // union region: bilinear tiles (18432B) / GA feature table (16384B)
    __shared__ __align__(16) char uraw[TQ * PITCH * 2 + TK * PITCH * 2];
    __shared__ float  bilS[TQ * BPITCH];
    __shared__ __align__(16) uint4 B4s[4 * 4 * 32];   // layer-2 B frag pairs, 8KB
    __shared__ __align__(8) float2 b1p[32], b2p[32];
    __shared__ uint   w3bp[32];
    __shared__ float  cxq[TQ], cyq[TQ], cxk[TK], cyk[TK];
    __shared__ int    aqs[TQ], aks[TK];
    __shared__ float  cadd;

    __nv_bfloat16* qWt = (__nv_bfloat16*)uraw;
    __nv_bfloat16* qt  = (__nv_bfloat16*)(uraw + TQ * PITCH * 2);
    uint*          GAs = (uint*)uraw;     // [16 k][64 row][4] bf16x2 feature pairs

    const int tid  = threadIdx.x;
    const int warp = tid >> 5;
    const int lane = tid & 31;
    const int m    = lane & 3;
    const int g    = lane >> 2;
    const int wq   = warp & 3;
    const int wk   = warp >> 2;
    const int b    = blockIdx.z;
    const int q0   = blockIdx.y * TQ;
    const int k0   = blockIdx.x * TK;

    if (tid < GH) {
        int i = tid;
        int gq = b * Qn + q0 + i;
        cxq[i] = coords[gq * 2 + 0]; cyq[i] = coords[gq * 2 + 1];
        aqs[i] = amask[gq];
    } else if (tid < 2 * GH) {
        int i = tid - GH;
        int gk = b * Qn + k0 + i;
        cxk[i] = coords[gk * 2 + 0]; cyk[i] = coords[gk * 2 + 1];
        aks[i] = amask[gk];
    }
    if (tid == 0) cadd = b3[0] + bias[0];

    // layer-2 B fragment pairs: entry (s, np, lane) -> frags n=2np, 2np+1
#pragma unroll
    for (int e = tid; e < 512; e += 256) {
        int s  = e >> 7;
        int np = (e >> 5) & 3;
        int ln = e & 31;
        int em = ln & 3, eg = ln >> 2;
        int kk = 16 * s + 2 * em;
        uint4 v;
        int n0 = 8 * (2 * np) + eg;
        v.x = packbf2(w2[kk * GH + n0],       w2[(kk + 1) * GH + n0]);
        v.y = packbf2(w2[(kk + 8) * GH + n0], w2[(kk + 9) * GH + n0]);
        int n1 = 8 * (2 * np + 1) + eg;
        v.z = packbf2(w2[kk * GH + n1],       w2[(kk + 1) * GH + n1]);
        v.w = packbf2(w2[(kk + 8) * GH + n1], w2[(kk + 9) * GH + n1]);
        B4s[e] = v;
    }
    if (tid < 32) {
        int nb = tid >> 2, mm = tid & 3;
        int c = 8 * nb + 2 * mm;
        b1p[tid]  = make_float2(b1[c], b1[c + 1]);
        b2p[tid]  = make_float2(b2[c], b2[c + 1]);
        w3bp[tid] = packbf2(w3[c], w3[c + 1]);
    }

    uint W1B[8];
#pragma unroll
    for (int nb = 0; nb < 8; nb++) {
        int nn = 8 * nb + g;
        W1B[nb] = (m < 3) ? packbf2(w1[(2 * m) * GH + nn], w1[(2 * m + 1) * GH + nn]) : 0u;
    }

    // ---- bilinear via mma ----
    float bacc[4][4];
#pragma unroll
    for (int n = 0; n < 4; n++)
#pragma unroll
        for (int j = 0; j < 4; j++) bacc[n][j] = 0.f;

#pragma unroll 1
    for (int d0 = 0; d0 < Dn; d0 += 64) {
        __syncthreads();
#pragma unroll
        for (int rep = 0; rep < 2; rep++) {
            int idx = tid + rep * 256;
            int r = idx >> 3, c8 = (idx & 7) * 8;
            *(uint4*)&qWt[r * PITCH + c8] =
                *(const uint4*)&g_qWb[(b * Qn + q0 + r) * Dn + d0 + c8];
            *(uint4*)&qt[r * PITCH + c8] =
                *(const uint4*)&g_qb[(b * Qn + k0 + r) * Dn + d0 + c8];
        }
        __syncthreads();
#pragma unroll
        for (int s2 = 0; s2 < 4; s2++) {
            const int acol = 16 * s2 + 2 * m;
            const int arow = 16 * wq + g;
            uint a0 = *(const uint*)&qWt[arow * PITCH + acol];
            uint a1 = *(const uint*)&qWt[(arow + 8) * PITCH + acol];
            uint a2 = *(const uint*)&qWt[arow * PITCH + acol + 8];
            uint a3 = *(const uint*)&qWt[(arow + 8) * PITCH + acol + 8];
#pragma unroll
            for (int n = 0; n < 4; n++) {
                const int brow = 32 * wk + 8 * n + g;
                uint b0 = *(const uint*)&qt[brow * PITCH + acol];
                uint b1v = *(const uint*)&qt[brow * PITCH + acol + 8];
                mma16816(bacc[n], a0, a1, a2, a3, b0, b1v);
            }
        }
    }
    __syncthreads();
#pragma unroll
    for (int n = 0; n < 4; n++) {
        int row = 16 * wq + g;
        int col = 32 * wk + 8 * n + 2 * m;
        *(float2*)&bilS[row * BPITCH + col]       = make_float2(bacc[n][0], bacc[n][1]);
        *(float2*)&bilS[(row + 8) * BPITCH + col] = make_float2(bacc[n][2], bacc[n][3]);
    }

    // ---- MLP phase: 4 passes of 16 k's; GA table overlays bilinear tiles ----
    const int row0 = 16 * wq + g;
    const int row1 = row0 + 8;
    const bool qa0 = (aqs[row0] != 0), qa1 = (aqs[row1] != 0);
    const float caddv = cadd;

#pragma unroll 1
    for (int p = 0; p < 4; p++) {
        __syncthreads();   // prior GA/tile reads done before overwrite
        // precompute GA features for k in [16p, 16p+16), all 64 rows
#pragma unroll
        for (int r = 0; r < 4; r++) {
            int e   = tid + 256 * r;        // 0..1023
            int kl  = e >> 6;               // 0..15
            int row = e & 63;
            int k   = 16 * p + kl;
            if (aks[k] != 0) {
                float dxv = cxq[row] - cxk[k];
                float dyv = cyq[row] - cyk[k];
                float d2v = fmaf(dxv, dxv, dyv * dyv);
                float dsv = sqrtf(d2v + 1e-8f);
                bool  mzv = (fabsf(dxv) < 1e-6f) && (fabsf(dyv) < 1e-6f);
                float xsv = mzv ? 1e-6f : dxv;
                float ysv = mzv ? 1e-6f : dyv;
                float rhv = rsqrtf(fmaf(xsv, xsv, ysv * ysv));
                uint4 gv;
                gv.x = packbf2(dxv, dyv);
                gv.y = packbf2(dsv, d2v);
                gv.z = packbf2(ysv * rhv, xsv * rhv);
                gv.w = 0u;
                *(uint4*)&GAs[(kl * 64 + row) * 4] = gv;
            }
        }
        __syncthreads();

#pragma unroll 1
        for (int i = 0; i < 8; i++) {
            const int kl = 8 * wk + i;
            const int k  = 16 * p + kl;
            const int gk = k0 + k;
            const int mw = i >> 1;          // writer lane in m-group

            if (aks[k] == 0) {
                if (m == mw) {
                    out[((long)(b * Qn + q0 + row0)) * Qn + gk] = -1e9f;
                    out[((long)(b * Qn + q0 + row1)) * Qn + gk] = -1e9f;
                }
                continue;
            }

            const uint GA0 = GAs[(kl * 64 + row0) * 4 + m];
            const uint GA1 = GAs[(kl * 64 + row1) * 4 + m];

            float acc2[8][4];
#pragma unroll
            for (int n = 0; n < 8; n++) {
                float2 bv = b2p[n * 4 + m];
                acc2[n][0] = bv.x; acc2[n][1] = bv.y;
                acc2[n][2] = bv.x; acc2[n][3] = bv.y;
            }

#pragma unroll
            for (int s = 0; s < 4; s++) {
                uint a0, a1, a2, a3;
                {
                    int nb = 2 * s;
                    float2 bv = b1p[nb * 4 + m];
                    float c0 = bv.x, c1 = bv.y, c2 = bv.x, c3 = bv.y;
                    mma16808(c0, c1, c2, c3, GA0, GA1, W1B[nb]);
                    a0 = silu2(packbf2(c0, c1));
                    a1 = silu2(packbf2(c2, c3));
                }
                {
                    int nb = 2 * s + 1;
                    float2 bv = b1p[nb * 4 + m];
                    float c0 = bv.x, c1 = bv.y, c2 = bv.x, c3 = bv.y;
                    mma16808(c0, c1, c2, c3, GA0, GA1, W1B[nb]);
                    a2 = silu2(packbf2(c0, c1));
                    a3 = silu2(packbf2(c2, c3));
                }
                const uint4* Brow = &B4s[(s * 4) * 32 + lane];
#pragma unroll
                for (int np = 0; np < 4; np++) {
                    uint4 Bv = Brow[np * 32];
                    mma16816(acc2[2 * np],     a0, a1, a2, a3, Bv.x, Bv.y);
                    mma16816(acc2[2 * np + 1], a0, a1, a2, a3, Bv.z, Bv.w);
                }
            }

            // epilogue: packed silu(h2) . w3
            uint P0 = 0u, P1 = 0u;
#pragma unroll
            for (int n = 0; n < 8; n++) {
                uint wv = w3bp[n * 4 + m];
                uint s01 = silu2(packbf2(acc2[n][0], acc2[n][1]));
                uint s23 = silu2(packbf2(acc2[n][2], acc2[n][3]));
                HFMA2BF(P0, s01, wv, P0);
                HFMA2BF(P1, s23, wv, P1);
            }
            float p0 = __uint_as_float(P0 << 16) + __uint_as_float(P0 & 0xffff0000u);
            float p1 = __uint_as_float(P1 << 16) + __uint_as_float(P1 & 0xffff0000u);
            p0 += __shfl_xor_sync(0xffffffffu, p0, 1);
            p0 += __shfl_xor_sync(0xffffffffu, p0, 2);
            p1 += __shfl_xor_sync(0xffffffffu, p1, 1);
            p1 += __shfl_xor_sync(0xffffffffu, p1, 2);

            if (m == mw) {
                const int qi0 = q0 + row0, qi1 = q0 + row1;
                float v0 = qa0 ? ((qi0 == gk) ? 0.f
                                  : p0 + bilS[row0 * BPITCH + k] + caddv) : -1e9f;
                float v1 = qa1 ? ((qi1 == gk) ? 0.f
                                  : p1 + bilS[row1 * BPITCH + k] + caddv) : -1e9f;
                out[((long)(b * Qn + qi0)) * Qn + gk] = v0;
                out[((long)(b * Qn + qi1)) * Qn + gk] = v1;
            }
        }
    }
}

// ---------------------------------------------------------------------------
extern "C" void kernel_launch(void* const* d_in, const int* in_sizes, int n_in,
                              void* d_out, int out_size)
{
    const float* q      = (const float*)d_in[0];
    const float* coords = (const float*)d_in[1];
    const int*   amask  = (const int*)d_in[2];
    const float* W      = (const float*)d_in[3];
    const float* w1     = (const float*)d_in[4];
    const float* b1     = (const float*)d_in[5];
    const float* w2     = (const float*)d_in[6];
    const float* b2     = (const float*)d_in[7];
    const float* w3     = (const float*)d_in[8];
    const float* b3     = (const float*)d_in[9];
    const float* bias   = (const float*)d_in[10];
    float* out = (float*)d_out;

    {
        dim3 grid((Bn * Qn) / 64, Dn / 64);
        prep_kernel<<<grid, 256>>>(q, W);
    }
    {
        dim3 grid(Qn / TK, Qn / TQ, Bn);
        edge_head_mma_kernel<<<grid, 256>>>(coords, amask,
                                            w1, b1, w2, b2, w3, b3, bias, out);
    }
}